// round 1
// baseline (speedup 1.0000x reference)
#include <cuda_runtime.h>
#include <math.h>

#define Nn 20000
#define Rr 400
#define Hh 200
#define Ee 200000
#define Tt 3
#define Bb 1024
#define Cc 50
#define CH (Cc*Hh)
#define SLOPEC 0.22916666666666666f
#define EPSN 1e-12f

// ---------------- scratch (device globals; no allocation allowed) ----------------
__device__ float g_ent[Nn*Hh];
__device__ float g_h1[Nn*Hh];
__device__ float g_h2[Nn*Hh];
__device__ float g_pre[Nn*Hh];
__device__ float g_S[Nn*Hh];
__device__ float g_U[Nn*Hh];
__device__ float g_winv[Nn];
__device__ float g_rnorm[Nn];
__device__ float g_relh[Rr*Hh];
__device__ float g_relent[Rr*Hh];
__device__ float g_x[Rr*2*Hh];
__device__ float g_gi[Rr*3*Hh];
__device__ float g_gh[Rr*3*Hh];
__device__ float g_nrel[Rr*Hh];
__device__ int   g_relCnt[Rr];
__device__ int   g_relBase[Rr+1];
__device__ int   g_relCur[Rr];
__device__ int   g_edgeByRel[Ee];
__device__ int   g_degCnt[Nn];
__device__ int   g_nodeBase[Nn+1];
__device__ int   g_nodeCur[Nn];
__device__ int   g_edgeByDst[Ee];
__device__ int   g_zeroList[Nn];
__device__ int   g_zeroCount;
__device__ float g_feat[Bb*CH];
__device__ float g_dec[Bb*Hh];
__device__ float g_e1[Bb*Hh];
__device__ float g_e2[Bb*Hh];

// ---------------- utility kernels ----------------

// out[r] = in[r] / max(||in[r]||, eps)   (one block per row)
__global__ void normalize_rows(const float* __restrict__ in, float* __restrict__ out, int rows) {
    int r = blockIdx.x;
    if (r >= rows) return;
    __shared__ float red[256];
    int t = threadIdx.x;
    float v = (t < Hh) ? in[r*Hh + t] : 0.f;
    red[t] = v*v;
    __syncthreads();
    for (int s = 128; s > 0; s >>= 1) { if (t < s) red[t] += red[t+s]; __syncthreads(); }
    float inv = 1.0f / fmaxf(sqrtf(red[0]), EPSN);
    if (t < Hh) out[r*Hh + t] = v * inv;
}

__global__ void zero_prep() {
    int i = blockIdx.x * blockDim.x + threadIdx.x;
    if (i < Nn) g_degCnt[i] = 0;
    if (i < Rr) g_relCnt[i] = 0;
    if (i == 0) g_zeroCount = 0;
}

__global__ void hist_kernel(const int* __restrict__ er, const int* __restrict__ ds) {
    int e = blockIdx.x * blockDim.x + threadIdx.x;
    if (e < Ee) {
        atomicAdd(&g_relCnt[er[e]], 1);
        atomicAdd(&g_degCnt[ds[e]], 1);
    }
}

__global__ void scan_rel() {
    if (threadIdx.x == 0) {
        int run = 0;
        for (int i = 0; i < Rr; i++) {
            int v = g_relCnt[i];
            g_relBase[i] = run; g_relCur[i] = run;
            run += v;
        }
        g_relBase[Rr] = run;
    }
}

__global__ void scan_node() {
    __shared__ int sm[1024];
    __shared__ int carry;
    int t = threadIdx.x;
    if (t == 0) carry = 0;
    __syncthreads();
    for (int base = 0; base < Nn; base += 1024) {
        int i = base + t;
        int v = (i < Nn) ? g_degCnt[i] : 0;
        sm[t] = v;
        __syncthreads();
        for (int off = 1; off < 1024; off <<= 1) {
            int y = (t >= off) ? sm[t - off] : 0;
            __syncthreads();
            sm[t] += y;
            __syncthreads();
        }
        int excl = sm[t] - v + carry;
        if (i < Nn) { g_nodeBase[i] = excl; g_nodeCur[i] = excl; }
        __syncthreads();
        if (t == 1023) carry += sm[1023];
        __syncthreads();
    }
    if (t == 0) g_nodeBase[Nn] = carry;
}

__global__ void scatter_edges(const int* __restrict__ er, const int* __restrict__ ds) {
    int e = blockIdx.x * blockDim.x + threadIdx.x;
    if (e < Ee) {
        int p1 = atomicAdd(&g_relCur[er[e]], 1);
        g_edgeByRel[p1] = e;
        int p2 = atomicAdd(&g_nodeCur[ds[e]], 1);
        g_edgeByDst[p2] = e;
    }
}

__global__ void build_misc() {
    int n = blockIdx.x * blockDim.x + threadIdx.x;
    if (n < Nn) {
        int d = g_degCnt[n];
        g_rnorm[n] = d > 0 ? 1.0f / (float)d : 0.0f;
        if (d == 0) {
            int i = atomicAdd(&g_zeroCount, 1);
            g_zeroList[i] = n;
        }
    }
}

// per-relation mean of ent[src[e]] over the sorted bucket  (no fp atomics)
__global__ void rel_mean(const int* __restrict__ srcT) {
    __shared__ int ss[256];
    int r = blockIdx.x, t = threadIdx.x;
    int b0 = g_relBase[r], b1 = g_relBase[r+1];
    float acc = 0.f;
    for (int cb = b0; cb < b1; cb += 256) {
        int m = min(256, b1 - cb);
        if (t < m) ss[t] = srcT[g_edgeByRel[cb + t]];
        __syncthreads();
        if (t < Hh) {
            int i = 0;
            for (; i + 3 < m; i += 4) {
                float a0 = g_ent[ss[i  ]*Hh + t];
                float a1 = g_ent[ss[i+1]*Hh + t];
                float a2 = g_ent[ss[i+2]*Hh + t];
                float a3 = g_ent[ss[i+3]*Hh + t];
                acc += a0 + a1 + a2 + a3;
            }
            for (; i < m; i++) acc += g_ent[ss[i]*Hh + t];
        }
        __syncthreads();
    }
    if (t < Hh) {
        int cnt = b1 - b0;
        g_relent[r*Hh + t] = cnt > 0 ? acc / (float)cnt : 0.f;
    }
}

__global__ void build_x(const float* __restrict__ rel_embeds) {
    int i = blockIdx.x * blockDim.x + threadIdx.x;
    if (i < Rr*2*Hh) {
        int r = i / (2*Hh), c = i % (2*Hh);
        g_x[i] = (c < Hh) ? rel_embeds[r*Hh + c] : g_relent[r*Hh + (c - Hh)];
    }
}

// GRU gates + l2norm of new hidden
__global__ void gru_gate() {
    int r = blockIdx.x, t = threadIdx.x;
    __shared__ float red[256];
    float hp = 0.f;
    if (t < Hh) {
        const float* gi = &g_gi[r*3*Hh];
        const float* gh = &g_gh[r*3*Hh];
        float h  = g_relh[r*Hh + t];
        float rr = 1.f / (1.f + expf(-(gi[t]        + gh[t])));
        float z  = 1.f / (1.f + expf(-(gi[Hh+t]     + gh[Hh+t])));
        float n  = tanhf(gi[2*Hh+t] + rr * gh[2*Hh+t]);
        hp = (1.f - z) * n + z * h;
    }
    red[t] = hp*hp;
    __syncthreads();
    for (int s = 128; s > 0; s >>= 1) { if (t < s) red[t] += red[t+s]; __syncthreads(); }
    float inv = 1.0f / fmaxf(sqrtf(red[0]), EPSN);
    if (t < Hh) g_nrel[r*Hh + t] = hp * inv;
}

// pre[n] = sum over edges into n of (h_in[src] + n_rel[erel])  (sorted, no atomics)
__global__ void gather_pre(const int* __restrict__ srcT, const int* __restrict__ erelT, int which) {
    const float* hin = which ? g_h1 : g_ent;
    __shared__ int ss[64];
    __shared__ int rs[64];
    int n = blockIdx.x, t = threadIdx.x;
    int b0 = g_nodeBase[n], b1 = g_nodeBase[n+1];
    float acc = 0.f;
    for (int cb = b0; cb < b1; cb += 64) {
        int m = min(64, b1 - cb);
        if (t < m) {
            int e = g_edgeByDst[cb + t];
            ss[t] = srcT[e];
            rs[t] = erelT[e];
        }
        __syncthreads();
        if (t < Hh) {
            for (int i = 0; i < m; i++)
                acc += hin[ss[i]*Hh + t] + g_nrel[rs[i]*Hh + t];
        }
        __syncthreads();
    }
    if (t < Hh) g_pre[n*Hh + t] = acc;
}

// deg==0 rows: out = rrelu(h_in @ Wel^T)
__global__ void fixup_zero(const float* __restrict__ Wel, int which) {
    const float* hin = which ? g_h1 : g_ent;
    float* out = which ? g_h2 : g_h1;
    __shared__ float hrow[Hh];
    for (int li = blockIdx.x; li < g_zeroCount; li += gridDim.x) {
        int n = g_zeroList[li];
        int t = threadIdx.x;
        if (t < Hh) hrow[t] = hin[n*Hh + t];
        __syncthreads();
        if (t < Hh) {
            float s = 0.f;
            for (int k = 0; k < Hh; k++) s += hrow[k] * Wel[t*Hh + k];
            out[n*Hh + t] = s >= 0.f ? s : SLOPEC * s;
        }
        __syncthreads();
    }
}

__global__ void rownorm_inv() {
    int row = blockIdx.x * 8 + (threadIdx.x >> 5);
    int lane = threadIdx.x & 31;
    if (row >= Nn) return;
    float s = 0.f;
    for (int c = lane; c < Hh; c += 32) { float v = g_h2[row*Hh + c]; s += v*v; }
    for (int o = 16; o > 0; o >>= 1) s += __shfl_xor_sync(0xffffffff, s, o);
    if (lane == 0) g_winv[row] = 1.0f / fmaxf(sqrtf(s), EPSN);
}

__global__ void update_ent() {
    int i = blockIdx.x * blockDim.x + threadIdx.x;
    if (i < Nn*Hh) {
        int row = i / Hh;
        float e = g_ent[i];
        float u = g_U[i];
        float w = g_h2[i] * g_winv[row];
        g_ent[i] = e + u * (w - e);
    }
}

__global__ void copy_relh() {
    int i = blockIdx.x * blockDim.x + threadIdx.x;
    if (i < Rr*Hh) g_relh[i] = g_nrel[i];
}

// ---------------- generic tiled GEMM: C = epi(A @ W^T) ----------------
// A: (M,K) row-major. W: (Nout,K) row-major. C: (M,Nout) row-major.
// EPI: 0 plain | 1 rrelu(rowscale[row]*acc + S) | 2 sigmoid(acc+bias) |
//      3 relu(acc+bias) | 4 acc+bias
template<int EPI>
__global__ void gemm_kernel(const float* __restrict__ A, const float* __restrict__ W,
                            float* __restrict__ C, int M, int Nout, int Kdim,
                            const float* __restrict__ bias,
                            const float* __restrict__ Sadd,
                            const float* __restrict__ rowscale) {
    __shared__ float As[16][64];
    __shared__ float Ws[16][64];
    int tx = threadIdx.x, ty = threadIdx.y;           // 16x16
    int tid = ty * 16 + tx;
    int j0 = blockIdx.x * 64;
    int i0 = blockIdx.y * 64;
    float acc[4][4];
#pragma unroll
    for (int a = 0; a < 4; a++)
#pragma unroll
        for (int b = 0; b < 4; b++) acc[a][b] = 0.f;

    for (int kt = 0; kt < Kdim; kt += 16) {
#pragma unroll
        for (int l = 0; l < 4; l++) {
            int idx = l * 256 + tid;
            int r = idx >> 4, k = idx & 15;
            int gr = i0 + r, gk = kt + k;
            As[k][r] = (gr < M && gk < Kdim) ? A[(size_t)gr * Kdim + gk] : 0.f;
            int wr = j0 + r;
            Ws[k][r] = (wr < Nout && gk < Kdim) ? W[(size_t)wr * Kdim + gk] : 0.f;
        }
        __syncthreads();
#pragma unroll
        for (int k = 0; k < 16; k++) {
            float4 a4 = *reinterpret_cast<const float4*>(&As[k][ty*4]);
            float4 w4 = *reinterpret_cast<const float4*>(&Ws[k][tx*4]);
            float av[4] = {a4.x, a4.y, a4.z, a4.w};
            float wv[4] = {w4.x, w4.y, w4.z, w4.w};
#pragma unroll
            for (int a = 0; a < 4; a++)
#pragma unroll
                for (int b = 0; b < 4; b++) acc[a][b] += av[a] * wv[b];
        }
        __syncthreads();
    }
#pragma unroll
    for (int a = 0; a < 4; a++) {
        int row = i0 + ty*4 + a;
        if (row >= M) continue;
#pragma unroll
        for (int b = 0; b < 4; b++) {
            int col = j0 + tx*4 + b;
            if (col >= Nout) continue;
            float v = acc[a][b];
            if (EPI == 1) {
                v = v * rowscale[row] + Sadd[(size_t)row * Nout + col];
                v = v >= 0.f ? v : SLOPEC * v;
            } else if (EPI == 2) {
                v += bias[col];
                v = 1.f / (1.f + expf(-v));
            } else if (EPI == 3) {
                v += bias[col];
                v = fmaxf(v, 0.f);
            } else if (EPI == 4) {
                v += bias[col];
            }
            C[(size_t)row * Nout + col] = v;
        }
    }
}

// ---------------- decoder ----------------

__global__ void dec_gather(const int* __restrict__ sidx, const int* __restrict__ oidx, int mode) {
    int i = blockIdx.x * blockDim.x + threadIdx.x;
    if (i < Bb*Hh) {
        int b = i / Hh, c = i % Hh;
        g_e1[i] = g_ent[sidx[b]*Hh + c];
        g_e2[i] = mode ? g_ent[oidx[b]*Hh + c] : g_relh[oidx[b]*Hh + c];
    }
}

__global__ void conv_feat(const float* __restrict__ cw, const float* __restrict__ cb) {
    int b = blockIdx.x;
    __shared__ float s1[Hh+2], s2[Hh+2];
    __shared__ float w[Cc*6];
    __shared__ float bb[Cc];
    int t = threadIdx.x;
    if (t < Hh) { s1[t+1] = g_e1[b*Hh + t]; s2[t+1] = g_e2[b*Hh + t]; }
    if (t == 0) { s1[0] = 0.f; s2[0] = 0.f; s1[Hh+1] = 0.f; s2[Hh+1] = 0.f; }
    for (int i = t; i < Cc*6; i += blockDim.x) w[i] = cw[i];
    if (t < Cc) bb[t] = cb[t];
    __syncthreads();
    for (int idx = t; idx < CH; idx += blockDim.x) {
        int c = idx / Hh, i = idx % Hh;
        const float* wc = &w[c*6];
        float v = bb[c]
            + s1[i]*wc[0] + s1[i+1]*wc[1] + s1[i+2]*wc[2]
            + s2[i]*wc[3] + s2[i+1]*wc[4] + s2[i+2]*wc[5];
        g_feat[(size_t)b*CH + idx] = fmaxf(v, 0.f);
    }
}

// ---------------- host ----------------

static void* symaddr(const void* s) { void* p = nullptr; cudaGetSymbolAddress(&p, s); return p; }

extern "C" void kernel_launch(void* const* d_in, const int* in_sizes, int n_in,
                              void* d_out, int out_size) {
    const float* ent_embeds = (const float*)d_in[0];
    const float* rel_embeds = (const float*)d_in[1];
    const float* Wr1  = (const float*)d_in[2];
    const float* Wsl1 = (const float*)d_in[3];
    const float* Wel1 = (const float*)d_in[4];
    const float* Wr2  = (const float*)d_in[5];
    const float* Wsl2 = (const float*)d_in[6];
    const float* Wel2 = (const float*)d_in[7];
    const float* lin_W = (const float*)d_in[8];
    const float* lin_b = (const float*)d_in[9];
    const float* gru_Wih = (const float*)d_in[10];
    const float* gru_Whh = (const float*)d_in[11];
    const float* gru_bih = (const float*)d_in[12];
    const float* gru_bhh = (const float*)d_in[13];
    const float* conve_w = (const float*)d_in[14];
    const float* conve_b = (const float*)d_in[15];
    const float* fce_w = (const float*)d_in[16];
    const float* fce_b = (const float*)d_in[17];
    const float* convr_w = (const float*)d_in[18];
    const float* convr_b = (const float*)d_in[19];
    const float* fcr_w = (const float*)d_in[20];
    const float* fcr_b = (const float*)d_in[21];
    const int* src  = (const int*)d_in[22];
    const int* dst  = (const int*)d_in[23];
    const int* erel = (const int*)d_in[24];
    const int* subj = (const int*)d_in[25];
    const int* relI = (const int*)d_in[26];
    const int* objI = (const int*)d_in[27];
    float* out = (float*)d_out;

    float* p_ent   = (float*)symaddr(g_ent);
    float* p_h1    = (float*)symaddr(g_h1);
    float* p_h2    = (float*)symaddr(g_h2);
    float* p_pre   = (float*)symaddr(g_pre);
    float* p_S     = (float*)symaddr(g_S);
    float* p_U     = (float*)symaddr(g_U);
    float* p_rnorm = (float*)symaddr(g_rnorm);
    float* p_relh  = (float*)symaddr(g_relh);
    float* p_x     = (float*)symaddr(g_x);
    float* p_gi    = (float*)symaddr(g_gi);
    float* p_gh    = (float*)symaddr(g_gh);
    float* p_feat  = (float*)symaddr(g_feat);
    float* p_dec   = (float*)symaddr(g_dec);

    dim3 t16(16, 16);

    // init: l2 normalize embeddings
    normalize_rows<<<Nn, 256>>>(ent_embeds, p_ent, Nn);
    normalize_rows<<<Rr, 256>>>(rel_embeds, p_relh, Rr);

    const float* Wr_[2]  = {Wr1, Wr2};
    const float* Wsl_[2] = {Wsl1, Wsl2};
    const float* Wel_[2] = {Wel1, Wel2};

    for (int t = 0; t < Tt; t++) {
        const int* srcT  = src  + t*Ee;
        const int* dstT  = dst  + t*Ee;
        const int* erelT = erel + t*Ee;

        zero_prep<<<(Nn + 255)/256, 256>>>();
        hist_kernel<<<(Ee + 255)/256, 256>>>(erelT, dstT);
        scan_rel<<<1, 32>>>();
        scan_node<<<1, 1024>>>();
        scatter_edges<<<(Ee + 255)/256, 256>>>(erelT, dstT);
        build_misc<<<(Nn + 255)/256, 256>>>();

        // relation-level GRU
        rel_mean<<<Rr, 256>>>(srcT);
        build_x<<<(Rr*2*Hh + 255)/256, 256>>>(rel_embeds);
        gemm_kernel<4><<<dim3((3*Hh+63)/64, (Rr+63)/64), t16>>>(p_x, gru_Wih, p_gi, Rr, 3*Hh, 2*Hh, gru_bih, nullptr, nullptr);
        gemm_kernel<4><<<dim3((3*Hh+63)/64, (Rr+63)/64), t16>>>(p_relh, gru_Whh, p_gh, Rr, 3*Hh, Hh, gru_bhh, nullptr, nullptr);
        gru_gate<<<Rr, 256>>>();

        // two RGCN layers (scatter-then-GEMM factorization)
        for (int l = 0; l < 2; l++) {
            const float* hin = (l == 0) ? p_ent : p_h1;
            float* hout = (l == 0) ? p_h1 : p_h2;
            gather_pre<<<Nn, 256>>>(srcT, erelT, l);
            gemm_kernel<0><<<dim3((Hh+63)/64, (Nn+63)/64), t16>>>(hin, Wsl_[l], p_S, Nn, Hh, Hh, nullptr, nullptr, nullptr);
            gemm_kernel<1><<<dim3((Hh+63)/64, (Nn+63)/64), t16>>>(p_pre, Wr_[l], hout, Nn, Hh, Hh, nullptr, p_S, p_rnorm);
            fixup_zero<<<64, 256>>>(Wel_[l], l);
        }

        // entity update
        rownorm_inv<<<(Nn + 7)/8, 256>>>();
        gemm_kernel<2><<<dim3((Hh+63)/64, (Nn+63)/64), t16>>>(p_ent, lin_W, p_U, Nn, Hh, Hh, lin_b, nullptr, nullptr);
        update_ent<<<(Nn*Hh + 255)/256, 256>>>();
        copy_relh<<<(Rr*Hh + 255)/256, 256>>>();
    }

    // ---- decoder: obj logits ----
    dec_gather<<<(Bb*Hh + 255)/256, 256>>>(subj, relI, 0);
    conv_feat<<<Bb, 256>>>(conve_w, conve_b);
    gemm_kernel<3><<<dim3((Hh+63)/64, (Bb+63)/64), t16>>>(p_feat, fce_w, p_dec, Bb, Hh, CH, fce_b, nullptr, nullptr);
    gemm_kernel<0><<<dim3((Nn+63)/64, (Bb+63)/64), t16>>>(p_dec, p_ent, out, Bb, Nn, Hh, nullptr, nullptr, nullptr);

    // ---- decoder: rel logits ----
    dec_gather<<<(Bb*Hh + 255)/256, 256>>>(subj, objI, 1);
    conv_feat<<<Bb, 256>>>(convr_w, convr_b);
    gemm_kernel<3><<<dim3((Hh+63)/64, (Bb+63)/64), t16>>>(p_feat, fcr_w, p_dec, Bb, Hh, CH, fcr_b, nullptr, nullptr);
    gemm_kernel<0><<<dim3((Rr+63)/64, (Bb+63)/64), t16>>>(p_dec, p_relh, out + (size_t)Bb*Nn, Bb, Rr, Hh, nullptr, nullptr, nullptr);
}